// round 15
// baseline (speedup 1.0000x reference)
#include <cuda_runtime.h>
#include <cuda_fp16.h>
#include <cstdint>
#include <cstddef>

// Problem dims (fixed by reference)
#define Bb 256
#define Tt 512
#define Dd 64
#define Ll 32
#define Hh 128
#define G4 512   // 4*H

// ---------------- scratch (device globals; no allocation allowed) ----------
__device__ __half g_pre16[(size_t)Bb * Tt * G4];   // 134 MB fp16 pre-acts

// ---------------- math helpers ---------------------------------------------
__device__ __forceinline__ float sigf(float x) {
    return __fdividef(1.0f, 1.0f + __expf(-x));
}
__device__ __forceinline__ float tanhf_fast(float x) {
    x = fminf(20.0f, fmaxf(-20.0f, x));
    float e = __expf(-2.0f * x);
    return __fdividef(1.0f - e, 1.0f + e);
}

// HMMA m16n8k16, fp16 inputs, fp32 accumulate
__device__ __forceinline__ void mma16816(
    float& c0, float& c1, float& c2, float& c3,
    uint32_t a0, uint32_t a1, uint32_t a2, uint32_t a3,
    uint32_t b0, uint32_t b1)
{
    asm volatile(
        "mma.sync.aligned.m16n8k16.row.col.f32.f16.f16.f32 "
        "{%0,%1,%2,%3}, {%4,%5,%6,%7}, {%8,%9}, {%0,%1,%2,%3};"
        : "+f"(c0), "+f"(c1), "+f"(c2), "+f"(c3)
        : "r"(a0), "r"(a1), "r"(a2), "r"(a3), "r"(b0), "r"(b1));
}

// ============================================================================
// Kernel 1: pre-GEMM on the tensor pipe (R14 body) — output now fp16.
// ============================================================================
#define PRE_MT 64
#define PRE_NT 128
#define XSTR 72
#define OFF_X16  0                       // 64*72 = 4608 halfs
#define OFF_W16  4608                    // 128*72 = 9216 halfs
#define OFF_SV   ((4608 + 9216) / 2)     // float index 6912
#define PRE_SMEM ((OFF_SV + 128) * 4)    // 28160 bytes

__global__ __launch_bounds__(256) void pre_kernel(
    const float* __restrict__ xd, const float* __restrict__ Wih,
    const float* __restrict__ xs, const float* __restrict__ Wzh,
    const float* __restrict__ bvec)
{
    extern __shared__ float sm[];
    __half* xsm = (__half*)sm + OFF_X16;     // [64 m][72 (64 k used)]
    __half* wsm = (__half*)sm + OFF_W16;     // [128 n][72 (64 k used)]
    float*  svrow = sm + OFF_SV;             // [128]

    int t  = threadIdx.x;
    int m0 = blockIdx.x * PRE_MT;
    int n0 = blockIdx.y * PRE_NT;
    int bb = m0 >> 9;   // T = 512

    {
        const float4* xg = (const float4*)(xd + (size_t)m0 * Dd);
#pragma unroll
        for (int i = t; i < PRE_MT * (Dd / 4); i += 256) {
            int row = i >> 4, dq = i & 15;
            float4 v = xg[row * 16 + dq];
            __half* dst = xsm + row * XSTR + dq * 4;
            *(__half2*)(dst)     = __floats2half2_rn(v.x, v.y);
            *(__half2*)(dst + 2) = __floats2half2_rn(v.z, v.w);
        }
    }
    {
        const float4* wg = (const float4*)(Wih + (size_t)n0 * Dd);
#pragma unroll
        for (int i = t; i < PRE_NT * (Dd / 4); i += 256) {
            int row = i >> 4, dq = i & 15;
            float4 v = wg[row * 16 + dq];
            __half* dst = wsm + row * XSTR + dq * 4;
            *(__half2*)(dst)     = __floats2half2_rn(v.x, v.y);
            *(__half2*)(dst + 2) = __floats2half2_rn(v.z, v.w);
        }
    }
    if (t < PRE_NT) {
        int gn = n0 + t;
        float acc = bvec[gn];
        const float* w = Wzh + gn * Ll;
        const float* xr = xs + bb * Ll;
#pragma unroll
        for (int l = 0; l < Ll; l++) acc += xr[l] * w[l];
        svrow[t] = acc;
    }
    __syncthreads();

    int wid  = t >> 5;
    int lane = t & 31;
    int wm   = wid >> 1;
    int wn   = wid & 1;
    int r    = lane >> 2;
    int cq   = (lane & 3) * 2;

    float c[8][4];
#pragma unroll
    for (int nf = 0; nf < 8; nf++)
#pragma unroll
        for (int q = 0; q < 4; q++) c[nf][q] = 0.0f;

    const __half* xw = xsm + (wm * 16 + r) * XSTR;

#pragma unroll
    for (int kc = 0; kc < 4; kc++) {
        int kb = kc * 16 + cq;
        uint32_t a0 = *(const uint32_t*)(xw + kb);
        uint32_t a1 = *(const uint32_t*)(xw + 8 * XSTR + kb);
        uint32_t a2 = *(const uint32_t*)(xw + kb + 8);
        uint32_t a3 = *(const uint32_t*)(xw + 8 * XSTR + kb + 8);
#pragma unroll
        for (int nf = 0; nf < 8; nf++) {
            const __half* bp = wsm + (wn * 64 + nf * 8 + r) * XSTR + kb;
            uint32_t b0 = *(const uint32_t*)(bp);
            uint32_t b1 = *(const uint32_t*)(bp + 8);
            mma16816(c[nf][0], c[nf][1], c[nf][2], c[nf][3],
                     a0, a1, a2, a3, b0, b1);
        }
    }

    // Epilogue: add static, store half2 pairs (rows r and r+8)
    int m_base = m0 + wm * 16 + r;
#pragma unroll
    for (int nf = 0; nf < 8; nf++) {
        int n_loc = wn * 64 + nf * 8 + cq;
        float2 sv = *(const float2*)(svrow + n_loc);
        __half* gp0 = g_pre16 + (size_t)m_base * G4 + n0 + n_loc;
        __half* gp1 = g_pre16 + (size_t)(m_base + 8) * G4 + n0 + n_loc;
        *(__half2*)gp0 = __floats2half2_rn(c[nf][0] + sv.x, c[nf][1] + sv.y);
        *(__half2*)gp1 = __floats2half2_rn(c[nf][2] + sv.x, c[nf][3] + sv.y);
    }
}

// ============================================================================
// Kernel 2: persistent LSTM scan — register-relief round.
//   R12/R13 structure, but ALL 16 W chunks live in smem (no whr registers):
//   frees ~20 regs below the 128 cap so ptxas can pipeline the LDS stream
//   deeper.  pre loads are now fp16 (g_pre16).
// ============================================================================
#define NWCH 16   // fp16 W chunks of 8 d-values (d 0..127, all in smem)
#define OFF_WH   0                        // 16*4096 halfs = 32768 floats
#define OFF_H16  32768                    // h16[2][128] fp16 = 128 floats
#define OFF_G    (OFF_H16 + 128)          // act[2][512] fp32
#define SCAN_SMEM ((OFF_G + 1024) * 4)    // 135680 bytes

__global__ void __launch_bounds__(512, 1)
scan_kernel(const float* __restrict__ Whh, const float* __restrict__ Wout,
            const float* __restrict__ bout, float* __restrict__ out)
{
    extern __shared__ float sm[];
    __half* whsm = (__half*)(sm + OFF_WH);    // [16 chunks][512 j][8 d] fp16
    __half* h16  = (__half*)(sm + OFF_H16);   // [2 rows][128 d] fp16
    int tid  = threadIdx.x;
    int b0   = blockIdx.x * 2;
    int j    = tid;                // gate-column index 0..511
    int wrp  = tid >> 5;
    int lane = tid & 31;
    bool is_tanh_gate = ((j >> 7) == 2);   // warp-uniform

    // ---- W d 0..127 -> fp16 smem: whsm[c][j][0..7]
#pragma unroll
    for (int c = 0; c < NWCH; c++) {
        float4 va = *(const float4*)(Whh + (size_t)j * 128 + c * 8);
        float4 vb = *(const float4*)(Whh + (size_t)j * 128 + c * 8 + 4);
        __half2 p0 = __floats2half2_rn(va.x, va.y);
        __half2 p1 = __floats2half2_rn(va.z, va.w);
        __half2 p2 = __floats2half2_rn(vb.x, vb.y);
        __half2 p3 = __floats2half2_rn(vb.z, vb.w);
        uint4 pk;
        pk.x = *(uint32_t*)&p0; pk.y = *(uint32_t*)&p1;
        pk.z = *(uint32_t*)&p2; pk.w = *(uint32_t*)&p3;
        *(uint4*)(whsm + (size_t)c * 4096 + j * 8) = pk;
    }
    if (tid < 256) h16[tid] = __float2half(0.0f);
    __syncthreads();

    int r2 = tid >> 7;        // row 0..1 (update role, tid < 256)
    int k  = tid & 127;       // hidden index (update role)

    float cst = 0.0f;
    float bo  = bout[0];
    float4 wo4 = make_float4(0.f, 0.f, 0.f, 0.f);
    if (wrp == 8 || wrp == 9) wo4 = *(const float4*)(Wout + lane * 4);

    const __half* pre0 = g_pre16 + ((size_t)(b0 + 0) * Tt) * G4 + j;
    const __half* pre1 = g_pre16 + ((size_t)(b0 + 1) * Tt) * G4 + j;

    const __half2 z2 = __float2half2_rn(0.0f);

    for (int t = 0; t < Tt; t++) {
        float p0 = __half2float(pre0[(size_t)t * G4]);
        float p1 = __half2float(pre1[(size_t)t * G4]);

        __half2 acc0[4], acc1[4];
#pragma unroll
        for (int i = 0; i < 4; i++) { acc0[i] = z2; acc1[i] = z2; }

#pragma unroll
        for (int c = 0; c < NWCH; c++) {         // d 0..127, all fp16 smem
            uint4 wp  = *(const uint4*)(whsm + (size_t)c * 4096 + j * 8);
            uint4 hp0 = *(const uint4*)(h16 + c * 8);
            uint4 hp1 = *(const uint4*)(h16 + 128 + c * 8);
            const __half2* w2 = (const __half2*)&wp;
            const __half2* a2 = (const __half2*)&hp0;
            const __half2* b2 = (const __half2*)&hp1;
            int ai = c & 3;
#pragma unroll
            for (int q = 0; q < 4; q++) {
                acc0[ai] = __hfma2(w2[q], a2[q], acc0[ai]);
                acc1[ai] = __hfma2(w2[q], b2[q], acc1[ai]);
            }
        }
        float2 m00 = __half22float2(acc0[0]), m01 = __half22float2(acc0[1]);
        float2 m02 = __half22float2(acc0[2]), m03 = __half22float2(acc0[3]);
        float2 m10 = __half22float2(acc1[0]), m11 = __half22float2(acc1[1]);
        float2 m12 = __half22float2(acc1[2]), m13 = __half22float2(acc1[3]);
        float g0 = p0 + ((m00.x + m00.y) + (m01.x + m01.y))
                      + ((m02.x + m02.y) + (m03.x + m03.y));
        float g1 = p1 + ((m10.x + m10.y) + (m11.x + m11.y))
                      + ((m12.x + m12.y) + (m13.x + m13.y));

        float act0, act1;
        if (is_tanh_gate) { act0 = tanhf_fast(g0); act1 = tanhf_fast(g1); }
        else              { act0 = sigf(g0);       act1 = sigf(g1);       }
        sm[OFF_G + 0 * 512 + j] = act0;
        sm[OFF_G + 1 * 512 + j] = act1;
        __syncthreads();   // barrier 1: acts visible

        if (tid < 256) {
            float ai = sm[OFF_G + r2 * 512 + k];
            float af = sm[OFF_G + r2 * 512 + 128 + k];
            float ag = sm[OFF_G + r2 * 512 + 256 + k];
            float ao = sm[OFF_G + r2 * 512 + 384 + k];
            cst = af * cst + ai * ag;
            float hval = ao * tanhf_fast(cst);
            h16[r2 * 128 + k] = __float2half(hval);
        }
        __syncthreads();   // barrier 2: h16 ready

        if (wrp == 8 || wrp == 9) {
            int row = wrp - 8;
            float2 ha = __half22float2(*(const __half2*)(h16 + row * 128 + lane * 4));
            float2 hb = __half22float2(*(const __half2*)(h16 + row * 128 + lane * 4 + 2));
            float v = ha.x * wo4.x + ha.y * wo4.y + hb.x * wo4.z + hb.y * wo4.w;
            v += __shfl_down_sync(0xffffffffu, v, 16);
            v += __shfl_down_sync(0xffffffffu, v, 8);
            v += __shfl_down_sync(0xffffffffu, v, 4);
            v += __shfl_down_sync(0xffffffffu, v, 2);
            v += __shfl_down_sync(0xffffffffu, v, 1);
            if (lane == 0) out[(size_t)(b0 + row) * Tt + t] = v + bo;
        }
    }
}

// ============================================================================
// launch
// ============================================================================
extern "C" void kernel_launch(void* const* d_in, const int* in_sizes, int n_in,
                              void* d_out, int out_size)
{
    const float* x_dyn = (const float*)d_in[0];
    const float* x_sta = (const float*)d_in[1];
    const float* W_ih  = (const float*)d_in[2];
    const float* W_hh  = (const float*)d_in[3];
    const float* W_zh  = (const float*)d_in[4];
    const float* bvec  = (const float*)d_in[5];
    const float* W_out = (const float*)d_in[6];
    const float* b_out = (const float*)d_in[7];
    float* out = (float*)d_out;

    (void)in_sizes; (void)n_in; (void)out_size;

    cudaFuncSetAttribute(pre_kernel,
                         cudaFuncAttributeMaxDynamicSharedMemorySize, PRE_SMEM);
    cudaFuncSetAttribute(scan_kernel,
                         cudaFuncAttributeMaxDynamicSharedMemorySize, SCAN_SMEM);

    dim3 pre_grid((Bb * Tt) / PRE_MT, G4 / PRE_NT);   // 2048 x 4
    pre_kernel<<<pre_grid, 256, PRE_SMEM>>>(x_dyn, W_ih, x_sta, W_zh, bvec);

    scan_kernel<<<128, 512, SCAN_SMEM>>>(W_hh, W_out, b_out, out);
}

// round 16
// speedup vs baseline: 1.0516x; 1.0516x over previous
#include <cuda_runtime.h>
#include <cuda_fp16.h>
#include <cstdint>
#include <cstddef>

// Problem dims (fixed by reference)
#define Bb 256
#define Tt 512
#define Dd 64
#define Ll 32
#define Hh 128
#define G4 512   // 4*H

// ---------------- scratch (device globals; no allocation allowed) ----------
__device__ __half g_pre16[(size_t)Bb * Tt * G4];   // 134 MB fp16 pre-acts

// ---------------- math helpers ---------------------------------------------
__device__ __forceinline__ float sigf(float x) {
    return __fdividef(1.0f, 1.0f + __expf(-x));
}
__device__ __forceinline__ float tanhf_fast(float x) {
    x = fminf(20.0f, fmaxf(-20.0f, x));
    float e = __expf(-2.0f * x);
    return __fdividef(1.0f - e, 1.0f + e);
}

// HMMA m16n8k16, fp16 inputs, fp32 accumulate
__device__ __forceinline__ void mma16816(
    float& c0, float& c1, float& c2, float& c3,
    uint32_t a0, uint32_t a1, uint32_t a2, uint32_t a3,
    uint32_t b0, uint32_t b1)
{
    asm volatile(
        "mma.sync.aligned.m16n8k16.row.col.f32.f16.f16.f32 "
        "{%0,%1,%2,%3}, {%4,%5,%6,%7}, {%8,%9}, {%0,%1,%2,%3};"
        : "+f"(c0), "+f"(c1), "+f"(c2), "+f"(c3)
        : "r"(a0), "r"(a1), "r"(a2), "r"(a3), "r"(b0), "r"(b1));
}

// ============================================================================
// Kernel 1: pre-GEMM on the tensor pipe — COALESCED-STORE round.
//   MMA body identical to R14.  Epilogue now bounces the output tile through
//   smem (fp16, stride 136 halfs: 16B-aligned rows, conflict-free fragment
//   writes) and streams it out as uint4 (256B contiguous per 16 lanes).
// ============================================================================
#define PRE_MT 64
#define PRE_NT 128
#define XSTR 72
#define OSTR 136                         // output stage stride (halfs)
#define OFF_X16  0                       // 64*72 = 4608 halfs
#define OFF_W16  4608                    // 128*72 = 9216 halfs
#define OFF_SV   ((4608 + 9216) / 2)     // float index 6912
#define PRE_SMEM ((OFF_SV + 128) * 4)    // 28160 bytes  (>= 64*136*2 = 17408)

__global__ __launch_bounds__(256) void pre_kernel(
    const float* __restrict__ xd, const float* __restrict__ Wih,
    const float* __restrict__ xs, const float* __restrict__ Wzh,
    const float* __restrict__ bvec)
{
    extern __shared__ float sm[];
    __half* xsm = (__half*)sm + OFF_X16;     // [64 m][72 (64 k used)]
    __half* wsm = (__half*)sm + OFF_W16;     // [128 n][72 (64 k used)]
    float*  svrow = sm + OFF_SV;             // [128]
    __half* osm = (__half*)sm;               // output stage, reused after MMA

    int t  = threadIdx.x;
    int m0 = blockIdx.x * PRE_MT;
    int n0 = blockIdx.y * PRE_NT;
    int bb = m0 >> 9;   // T = 512

    {
        const float4* xg = (const float4*)(xd + (size_t)m0 * Dd);
#pragma unroll
        for (int i = t; i < PRE_MT * (Dd / 4); i += 256) {
            int row = i >> 4, dq = i & 15;
            float4 v = xg[row * 16 + dq];
            __half* dst = xsm + row * XSTR + dq * 4;
            *(__half2*)(dst)     = __floats2half2_rn(v.x, v.y);
            *(__half2*)(dst + 2) = __floats2half2_rn(v.z, v.w);
        }
    }
    {
        const float4* wg = (const float4*)(Wih + (size_t)n0 * Dd);
#pragma unroll
        for (int i = t; i < PRE_NT * (Dd / 4); i += 256) {
            int row = i >> 4, dq = i & 15;
            float4 v = wg[row * 16 + dq];
            __half* dst = wsm + row * XSTR + dq * 4;
            *(__half2*)(dst)     = __floats2half2_rn(v.x, v.y);
            *(__half2*)(dst + 2) = __floats2half2_rn(v.z, v.w);
        }
    }
    if (t < PRE_NT) {
        int gn = n0 + t;
        float acc = bvec[gn];
        const float* w = Wzh + gn * Ll;
        const float* xr = xs + bb * Ll;
#pragma unroll
        for (int l = 0; l < Ll; l++) acc += xr[l] * w[l];
        svrow[t] = acc;
    }
    __syncthreads();

    int wid  = t >> 5;
    int lane = t & 31;
    int wm   = wid >> 1;
    int wn   = wid & 1;
    int r    = lane >> 2;
    int cq   = (lane & 3) * 2;

    float c[8][4];
#pragma unroll
    for (int nf = 0; nf < 8; nf++)
#pragma unroll
        for (int q = 0; q < 4; q++) c[nf][q] = 0.0f;

    const __half* xw = xsm + (wm * 16 + r) * XSTR;

#pragma unroll
    for (int kc = 0; kc < 4; kc++) {
        int kb = kc * 16 + cq;
        uint32_t a0 = *(const uint32_t*)(xw + kb);
        uint32_t a1 = *(const uint32_t*)(xw + 8 * XSTR + kb);
        uint32_t a2 = *(const uint32_t*)(xw + kb + 8);
        uint32_t a3 = *(const uint32_t*)(xw + 8 * XSTR + kb + 8);
#pragma unroll
        for (int nf = 0; nf < 8; nf++) {
            const __half* bp = wsm + (wn * 64 + nf * 8 + r) * XSTR + kb;
            uint32_t b0 = *(const uint32_t*)(bp);
            uint32_t b1 = *(const uint32_t*)(bp + 8);
            mma16816(c[nf][0], c[nf][1], c[nf][2], c[nf][3],
                     a0, a1, a2, a3, b0, b1);
        }
    }

    // static addend (register copies before smem reuse clobbers svrow? no —
    // svrow lives above the 17408B stage region; reads are safe, but order
    // via barrier anyway)
    __syncthreads();   // all warps done reading xsm/wsm (stage reuses them)

    // stage fragments in smem (fp16, stride 136: conflict-free, 16B rows)
    int m_loc = wm * 16 + r;
#pragma unroll
    for (int nf = 0; nf < 8; nf++) {
        int n_loc = wn * 64 + nf * 8 + cq;
        float2 sv = *(const float2*)(svrow + n_loc);
        *(__half2*)(osm + m_loc * OSTR + n_loc) =
            __floats2half2_rn(c[nf][0] + sv.x, c[nf][1] + sv.y);
        *(__half2*)(osm + (m_loc + 8) * OSTR + n_loc) =
            __floats2half2_rn(c[nf][2] + sv.x, c[nf][3] + sv.y);
    }
    __syncthreads();

    // coalesced stream-out: 1024 uint4 (8 halfs each), 4 per thread
#pragma unroll
    for (int q = 0; q < 4; q++) {
        int idx = t + 256 * q;          // 0..1023
        int row = idx >> 4;             // 0..63
        int seg = idx & 15;             // 0..15 (8 halfs each)
        uint4 v = *(const uint4*)(osm + row * OSTR + seg * 8);
        *(uint4*)(g_pre16 + (size_t)(m0 + row) * G4 + n0 + seg * 8) = v;
    }
}

// ============================================================================
// Kernel 2: persistent LSTM scan — R14 body restored (best: 685us):
//   12 smem W chunks + 16 half2 W regs, fp16 h, acts in matvec threads,
//   O-head off the critical path on warps 8,9.  pre loads fp16 (g_pre16).
// ============================================================================
#define NWCH 12   // fp16 W chunks of 8 d-values (d 0..95)
#define OFF_WH   0                        // 12*4096 halfs = 24576 floats
#define OFF_H16  24576                    // h16[2][128] fp16 = 128 floats
#define OFF_G    (OFF_H16 + 128)          // act[2][512] fp32
#define SCAN_SMEM ((OFF_G + 1024) * 4)    // 102912 bytes

__global__ void __launch_bounds__(512, 1)
scan_kernel(const float* __restrict__ Whh, const float* __restrict__ Wout,
            const float* __restrict__ bout, float* __restrict__ out)
{
    extern __shared__ float sm[];
    __half* whsm = (__half*)(sm + OFF_WH);    // [12 chunks][512 j][8 d] fp16
    __half* h16  = (__half*)(sm + OFF_H16);   // [2 rows][128 d] fp16
    int tid  = threadIdx.x;
    int b0   = blockIdx.x * 2;
    int j    = tid;                // gate-column index 0..511
    int wrp  = tid >> 5;
    int lane = tid & 31;
    bool is_tanh_gate = ((j >> 7) == 2);   // warp-uniform

    // ---- W d 0..95 -> fp16 smem: whsm[c][j][0..7]
#pragma unroll
    for (int c = 0; c < NWCH; c++) {
        float4 va = *(const float4*)(Whh + (size_t)j * 128 + c * 8);
        float4 vb = *(const float4*)(Whh + (size_t)j * 128 + c * 8 + 4);
        __half2 p0 = __floats2half2_rn(va.x, va.y);
        __half2 p1 = __floats2half2_rn(va.z, va.w);
        __half2 p2 = __floats2half2_rn(vb.x, vb.y);
        __half2 p3 = __floats2half2_rn(vb.z, vb.w);
        uint4 pk;
        pk.x = *(uint32_t*)&p0; pk.y = *(uint32_t*)&p1;
        pk.z = *(uint32_t*)&p2; pk.w = *(uint32_t*)&p3;
        *(uint4*)(whsm + (size_t)c * 4096 + j * 8) = pk;
    }
    // ---- W d 96..127 as 16 half2 registers
    __half2 whr[16];
    {
        const float* ws = Whh + (size_t)j * 128 + 96;
#pragma unroll
        for (int c = 0; c < 16; c++)
            whr[c] = __floats2half2_rn(ws[2 * c], ws[2 * c + 1]);
    }
    if (tid < 256) h16[tid] = __float2half(0.0f);
    __syncthreads();

    int r2 = tid >> 7;        // row 0..1 (update role, tid < 256)
    int k  = tid & 127;       // hidden index (update role)

    float cst = 0.0f;
    float bo  = bout[0];
    float4 wo4 = make_float4(0.f, 0.f, 0.f, 0.f);
    if (wrp == 8 || wrp == 9) wo4 = *(const float4*)(Wout + lane * 4);

    const __half* pre0 = g_pre16 + ((size_t)(b0 + 0) * Tt) * G4 + j;
    const __half* pre1 = g_pre16 + ((size_t)(b0 + 1) * Tt) * G4 + j;

    const __half2 z2 = __float2half2_rn(0.0f);

    for (int t = 0; t < Tt; t++) {
        float p0 = __half2float(pre0[(size_t)t * G4]);
        float p1 = __half2float(pre1[(size_t)t * G4]);

        __half2 acc0[4], acc1[4];
#pragma unroll
        for (int i = 0; i < 4; i++) { acc0[i] = z2; acc1[i] = z2; }

#pragma unroll
        for (int c = 0; c < NWCH; c++) {         // d 0..95 (fp16 smem weights)
            uint4 wp  = *(const uint4*)(whsm + (size_t)c * 4096 + j * 8);
            uint4 hp0 = *(const uint4*)(h16 + c * 8);
            uint4 hp1 = *(const uint4*)(h16 + 128 + c * 8);
            const __half2* w2 = (const __half2*)&wp;
            const __half2* a2 = (const __half2*)&hp0;
            const __half2* b2 = (const __half2*)&hp1;
            int ai = c & 3;
#pragma unroll
            for (int q = 0; q < 4; q++) {
                acc0[ai] = __hfma2(w2[q], a2[q], acc0[ai]);
                acc1[ai] = __hfma2(w2[q], b2[q], acc1[ai]);
            }
        }
#pragma unroll
        for (int c = 0; c < 4; c++) {            // d 96..127 (register weights)
            uint4 hp0 = *(const uint4*)(h16 + 96 + c * 8);
            uint4 hp1 = *(const uint4*)(h16 + 128 + 96 + c * 8);
            const __half2* a2 = (const __half2*)&hp0;
            const __half2* b2 = (const __half2*)&hp1;
#pragma unroll
            for (int q = 0; q < 4; q++) {
                acc0[c] = __hfma2(whr[4 * c + q], a2[q], acc0[c]);
                acc1[c] = __hfma2(whr[4 * c + q], b2[q], acc1[c]);
            }
        }
        float2 m00 = __half22float2(acc0[0]), m01 = __half22float2(acc0[1]);
        float2 m02 = __half22float2(acc0[2]), m03 = __half22float2(acc0[3]);
        float2 m10 = __half22float2(acc1[0]), m11 = __half22float2(acc1[1]);
        float2 m12 = __half22float2(acc1[2]), m13 = __half22float2(acc1[3]);
        float g0 = p0 + ((m00.x + m00.y) + (m01.x + m01.y))
                      + ((m02.x + m02.y) + (m03.x + m03.y));
        float g1 = p1 + ((m10.x + m10.y) + (m11.x + m11.y))
                      + ((m12.x + m12.y) + (m13.x + m13.y));

        float act0, act1;
        if (is_tanh_gate) { act0 = tanhf_fast(g0); act1 = tanhf_fast(g1); }
        else              { act0 = sigf(g0);       act1 = sigf(g1);       }
        sm[OFF_G + 0 * 512 + j] = act0;
        sm[OFF_G + 1 * 512 + j] = act1;
        __syncthreads();   // barrier 1: acts visible

        if (tid < 256) {
            float ai = sm[OFF_G + r2 * 512 + k];
            float af = sm[OFF_G + r2 * 512 + 128 + k];
            float ag = sm[OFF_G + r2 * 512 + 256 + k];
            float ao = sm[OFF_G + r2 * 512 + 384 + k];
            cst = af * cst + ai * ag;
            float hval = ao * tanhf_fast(cst);
            h16[r2 * 128 + k] = __float2half(hval);
        }
        __syncthreads();   // barrier 2: h16 ready

        if (wrp == 8 || wrp == 9) {
            int row = wrp - 8;
            float2 ha = __half22float2(*(const __half2*)(h16 + row * 128 + lane * 4));
            float2 hb = __half22float2(*(const __half2*)(h16 + row * 128 + lane * 4 + 2));
            float v = ha.x * wo4.x + ha.y * wo4.y + hb.x * wo4.z + hb.y * wo4.w;
            v += __shfl_down_sync(0xffffffffu, v, 16);
            v += __shfl_down_sync(0xffffffffu, v, 8);
            v += __shfl_down_sync(0xffffffffu, v, 4);
            v += __shfl_down_sync(0xffffffffu, v, 2);
            v += __shfl_down_sync(0xffffffffu, v, 1);
            if (lane == 0) out[(size_t)(b0 + row) * Tt + t] = v + bo;
        }
    }
}

// ============================================================================
// launch
// ============================================================================
extern "C" void kernel_launch(void* const* d_in, const int* in_sizes, int n_in,
                              void* d_out, int out_size)
{
    const float* x_dyn = (const float*)d_in[0];
    const float* x_sta = (const float*)d_in[1];
    const float* W_ih  = (const float*)d_in[2];
    const float* W_hh  = (const float*)d_in[3];
    const float* W_zh  = (const float*)d_in[4];
    const float* bvec  = (const float*)d_in[5];
    const float* W_out = (const float*)d_in[6];
    const float* b_out = (const float*)d_in[7];
    float* out = (float*)d_out;

    (void)in_sizes; (void)n_in; (void)out_size;

    cudaFuncSetAttribute(pre_kernel,
                         cudaFuncAttributeMaxDynamicSharedMemorySize, PRE_SMEM);
    cudaFuncSetAttribute(scan_kernel,
                         cudaFuncAttributeMaxDynamicSharedMemorySize, SCAN_SMEM);

    dim3 pre_grid((Bb * Tt) / PRE_MT, G4 / PRE_NT);   // 2048 x 4
    pre_kernel<<<pre_grid, 256, PRE_SMEM>>>(x_dyn, W_ih, x_sta, W_zh, bvec);

    scan_kernel<<<128, 512, SCAN_SMEM>>>(W_hh, W_out, b_out, out);
}

// round 17
// speedup vs baseline: 1.1718x; 1.1142x over previous
#include <cuda_runtime.h>
#include <cuda_fp16.h>
#include <cstdint>
#include <cstddef>

// Problem dims (fixed by reference)
#define Bb 256
#define Tt 512
#define Dd 64
#define Ll 32
#define Hh 128
#define G4 512   // 4*H

// ---------------- scratch (device globals; no allocation allowed) ----------
__device__ __half g_pre16[(size_t)Bb * Tt * G4];   // 134 MB fp16 pre-acts

// ---------------- math helpers ---------------------------------------------
__device__ __forceinline__ float sigf(float x) {
    return __fdividef(1.0f, 1.0f + __expf(-x));
}
__device__ __forceinline__ float tanhf_fast(float x) {
    x = fminf(20.0f, fmaxf(-20.0f, x));
    float e = __expf(-2.0f * x);
    return __fdividef(1.0f - e, 1.0f + e);
}

// HMMA m16n8k16, fp16 inputs, fp32 accumulate
__device__ __forceinline__ void mma16816(
    float& c0, float& c1, float& c2, float& c3,
    uint32_t a0, uint32_t a1, uint32_t a2, uint32_t a3,
    uint32_t b0, uint32_t b1)
{
    asm volatile(
        "mma.sync.aligned.m16n8k16.row.col.f32.f16.f16.f32 "
        "{%0,%1,%2,%3}, {%4,%5,%6,%7}, {%8,%9}, {%0,%1,%2,%3};"
        : "+f"(c0), "+f"(c1), "+f"(c2), "+f"(c3)
        : "r"(a0), "r"(a1), "r"(a2), "r"(a3), "r"(b0), "r"(b1));
}

// ============================================================================
// FUSED kernel: per-CTA pre-GEMM prologue (tensor pipe) + persistent scan.
//   Each CTA owns batch rows b0, b0+1.  Prologue computes this CTA's 1MB
//   slice of g_pre16 (M=1024, N=512, K=64) with the R14-proven HMMA mapping
//   and R16's coalesced staged store; then the unchanged R16 scan runs.
//
//   Prologue smem (half indices unless noted):
//     wsm16: [512 n][72]        73728 B   (W_ih fp16, resident all 16 iters)
//     xsm:   [64 m][72]          9216 B   (x tile per iteration)
//     svrow: float[2][512]       4096 B   (static part per row)
//     osm:   [64 m][520]        66560 B   (coalescing stage)   total 153600 B
//   Scan smem overlays the same region after a barrier (103 KB).
// ============================================================================
#define XSTR 72
#define OSTR 520
// prologue offsets
#define P_W16   0                         // halfs: 0 .. 36864
#define P_X16   36864                     // halfs: .. 41472
#define P_SV    20736                     // float idx (= 41472 halfs)
#define P_OSM   76800                     // halfs (= 87040+... : 87040B/2? no)
// byte-accurate: svrow ends at 41472*2 + 4096 = 87040 B -> osm half idx 43520
#undef  P_OSM
#define P_OSM   43520                     // halfs: 87040 B .. 153600 B
// scan offsets (float indices, as in R16)
#define NWCH 12
#define OFF_WH   0                        // whsm: 12*4096 halfs = 98304 B
#define OFF_H16  24576                    // float idx (98304 B)
#define OFF_G    (OFF_H16 + 128)
#define FUSED_SMEM 153600

__global__ void __launch_bounds__(512, 1)
fused_kernel(const float* __restrict__ xd,  const float* __restrict__ Wih,
             const float* __restrict__ xs,  const float* __restrict__ Wzh,
             const float* __restrict__ bvec,
             const float* __restrict__ Whh, const float* __restrict__ Wout,
             const float* __restrict__ bout, float* __restrict__ out)
{
    extern __shared__ float sm[];
    int tid  = threadIdx.x;
    int b0   = blockIdx.x * 2;
    int lane = tid & 31;
    int wid  = tid >> 5;

    // ======================= PROLOGUE: pre-GEMM =======================
    {
        __half* wsm16 = (__half*)sm + P_W16;
        __half* xsm   = (__half*)sm + P_X16;
        float*  svrow = sm + P_SV;
        __half* osm   = (__half*)sm + P_OSM;

        // W_ih [512][64] -> fp16 smem (once)
        {
            const float4* wg = (const float4*)Wih;
            for (int i = tid; i < 512 * 16; i += 512) {
                int row = i >> 4, dq = i & 15;
                float4 v = wg[row * 16 + dq];
                __half* dst = wsm16 + row * XSTR + dq * 4;
                *(__half2*)(dst)     = __floats2half2_rn(v.x, v.y);
                *(__half2*)(dst + 2) = __floats2half2_rn(v.z, v.w);
            }
        }
        // static part for both rows
        {
            int jj = tid;
#pragma unroll
            for (int rr = 0; rr < 2; rr++) {
                float acc = bvec[jj];
                const float* w  = Wzh + jj * Ll;
                const float* xr = xs + (b0 + rr) * Ll;
#pragma unroll
                for (int l = 0; l < Ll; l++) acc += xr[l] * w[l];
                svrow[rr * 512 + jj] = acc;
            }
        }
        __syncthreads();

        int wm = wid >> 3;           // 0..1 : M32 group
        int wn = wid & 7;            // 0..7 : N64 group
        int r  = lane >> 2;          // 0..7
        int cq = (lane & 3) * 2;     // 0,2,4,6

        for (int it = 0; it < 16; it++) {
            int rr = it >> 3;                // batch row 0/1
            int t0 = (it & 7) * 64;          // t block base

            // x tile [64 t][64 k] -> fp16
            {
                const float4* xg =
                    (const float4*)(xd + ((size_t)(b0 + rr) * Tt + t0) * Dd);
#pragma unroll
                for (int q = 0; q < 2; q++) {
                    int idx = tid + 512 * q;
                    int row = idx >> 4, dq = idx & 15;
                    float4 v = xg[row * 16 + dq];
                    __half* dst = xsm + row * XSTR + dq * 4;
                    *(__half2*)(dst)     = __floats2half2_rn(v.x, v.y);
                    *(__half2*)(dst + 2) = __floats2half2_rn(v.z, v.w);
                }
            }
            __syncthreads();   // xsm ready; osm free (prev stream done)

            float c[2][8][4];
#pragma unroll
            for (int mf = 0; mf < 2; mf++)
#pragma unroll
                for (int nf = 0; nf < 8; nf++)
#pragma unroll
                    for (int q = 0; q < 4; q++) c[mf][nf][q] = 0.0f;

#pragma unroll
            for (int kc = 0; kc < 4; kc++) {
                int kb = kc * 16 + cq;
                uint32_t a[2][4];
#pragma unroll
                for (int mf = 0; mf < 2; mf++) {
                    const __half* xw = xsm + (wm * 32 + mf * 16 + r) * XSTR;
                    a[mf][0] = *(const uint32_t*)(xw + kb);
                    a[mf][1] = *(const uint32_t*)(xw + 8 * XSTR + kb);
                    a[mf][2] = *(const uint32_t*)(xw + kb + 8);
                    a[mf][3] = *(const uint32_t*)(xw + 8 * XSTR + kb + 8);
                }
#pragma unroll
                for (int nf = 0; nf < 8; nf++) {
                    const __half* bp =
                        wsm16 + (wn * 64 + nf * 8 + r) * XSTR + kb;
                    uint32_t bb0 = *(const uint32_t*)(bp);
                    uint32_t bb1 = *(const uint32_t*)(bp + 8);
                    mma16816(c[0][nf][0], c[0][nf][1], c[0][nf][2], c[0][nf][3],
                             a[0][0], a[0][1], a[0][2], a[0][3], bb0, bb1);
                    mma16816(c[1][nf][0], c[1][nf][1], c[1][nf][2], c[1][nf][3],
                             a[1][0], a[1][1], a[1][2], a[1][3], bb0, bb1);
                }
            }

            // stage fragments (conflict-free: stride 520 halfs)
#pragma unroll
            for (int mf = 0; mf < 2; mf++) {
                int m_loc = wm * 32 + mf * 16 + r;
#pragma unroll
                for (int nf = 0; nf < 8; nf++) {
                    int n_loc = wn * 64 + nf * 8 + cq;
                    float2 sv = *(const float2*)(svrow + rr * 512 + n_loc);
                    *(__half2*)(osm + m_loc * OSTR + n_loc) =
                        __floats2half2_rn(c[mf][nf][0] + sv.x,
                                          c[mf][nf][1] + sv.y);
                    *(__half2*)(osm + (m_loc + 8) * OSTR + n_loc) =
                        __floats2half2_rn(c[mf][nf][2] + sv.x,
                                          c[mf][nf][3] + sv.y);
                }
            }
            __syncthreads();   // osm staged; xsm consumed

            // coalesced stream-out: 4096 uint4, 8 per thread
#pragma unroll
            for (int q = 0; q < 8; q++) {
                int idx = tid + 512 * q;
                int row = idx >> 6;      // 0..63
                int seg = idx & 63;      // 0..63 (8 halfs each)
                uint4 v = *(const uint4*)(osm + row * OSTR + seg * 8);
                *(uint4*)(g_pre16 +
                          ((size_t)(b0 + rr) * Tt + t0 + row) * G4 + seg * 8) = v;
            }
        }
        __syncthreads();   // prologue done; smem free for scan overlay
    }

    // ======================= SCAN (R16 body, unchanged) =======================
    __half* whsm = (__half*)(sm + OFF_WH);    // [12 chunks][512 j][8 d] fp16
    __half* h16  = (__half*)(sm + OFF_H16);   // [2 rows][128 d] fp16
    int j   = tid;
    int wrp = wid;
    bool is_tanh_gate = ((j >> 7) == 2);   // warp-uniform

    // W_hh d 0..95 -> fp16 smem
#pragma unroll
    for (int c = 0; c < NWCH; c++) {
        float4 va = *(const float4*)(Whh + (size_t)j * 128 + c * 8);
        float4 vb = *(const float4*)(Whh + (size_t)j * 128 + c * 8 + 4);
        __half2 p0 = __floats2half2_rn(va.x, va.y);
        __half2 p1 = __floats2half2_rn(va.z, va.w);
        __half2 p2 = __floats2half2_rn(vb.x, vb.y);
        __half2 p3 = __floats2half2_rn(vb.z, vb.w);
        uint4 pk;
        pk.x = *(uint32_t*)&p0; pk.y = *(uint32_t*)&p1;
        pk.z = *(uint32_t*)&p2; pk.w = *(uint32_t*)&p3;
        *(uint4*)(whsm + (size_t)c * 4096 + j * 8) = pk;
    }
    // W_hh d 96..127 as 16 half2 registers
    __half2 whr[16];
    {
        const float* ws = Whh + (size_t)j * 128 + 96;
#pragma unroll
        for (int c = 0; c < 16; c++)
            whr[c] = __floats2half2_rn(ws[2 * c], ws[2 * c + 1]);
    }
    if (tid < 256) h16[tid] = __float2half(0.0f);
    __syncthreads();

    int r2 = tid >> 7;
    int k  = tid & 127;

    float cst = 0.0f;
    float bo  = bout[0];
    float4 wo4 = make_float4(0.f, 0.f, 0.f, 0.f);
    if (wrp == 8 || wrp == 9) wo4 = *(const float4*)(Wout + lane * 4);

    const __half* pre0 = g_pre16 + ((size_t)(b0 + 0) * Tt) * G4 + j;
    const __half* pre1 = g_pre16 + ((size_t)(b0 + 1) * Tt) * G4 + j;

    const __half2 z2 = __float2half2_rn(0.0f);

    for (int t = 0; t < Tt; t++) {
        float p0 = __half2float(pre0[(size_t)t * G4]);
        float p1 = __half2float(pre1[(size_t)t * G4]);

        __half2 acc0[4], acc1[4];
#pragma unroll
        for (int i = 0; i < 4; i++) { acc0[i] = z2; acc1[i] = z2; }

#pragma unroll
        for (int c = 0; c < NWCH; c++) {         // d 0..95 (fp16 smem weights)
            uint4 wp  = *(const uint4*)(whsm + (size_t)c * 4096 + j * 8);
            uint4 hp0 = *(const uint4*)(h16 + c * 8);
            uint4 hp1 = *(const uint4*)(h16 + 128 + c * 8);
            const __half2* w2 = (const __half2*)&wp;
            const __half2* a2 = (const __half2*)&hp0;
            const __half2* b2 = (const __half2*)&hp1;
            int ai = c & 3;
#pragma unroll
            for (int q = 0; q < 4; q++) {
                acc0[ai] = __hfma2(w2[q], a2[q], acc0[ai]);
                acc1[ai] = __hfma2(w2[q], b2[q], acc1[ai]);
            }
        }
#pragma unroll
        for (int c = 0; c < 4; c++) {            // d 96..127 (register weights)
            uint4 hp0 = *(const uint4*)(h16 + 96 + c * 8);
            uint4 hp1 = *(const uint4*)(h16 + 128 + 96 + c * 8);
            const __half2* a2 = (const __half2*)&hp0;
            const __half2* b2 = (const __half2*)&hp1;
#pragma unroll
            for (int q = 0; q < 4; q++) {
                acc0[c] = __hfma2(whr[4 * c + q], a2[q], acc0[c]);
                acc1[c] = __hfma2(whr[4 * c + q], b2[q], acc1[c]);
            }
        }
        float2 m00 = __half22float2(acc0[0]), m01 = __half22float2(acc0[1]);
        float2 m02 = __half22float2(acc0[2]), m03 = __half22float2(acc0[3]);
        float2 m10 = __half22float2(acc1[0]), m11 = __half22float2(acc1[1]);
        float2 m12 = __half22float2(acc1[2]), m13 = __half22float2(acc1[3]);
        float g0 = p0 + ((m00.x + m00.y) + (m01.x + m01.y))
                      + ((m02.x + m02.y) + (m03.x + m03.y));
        float g1 = p1 + ((m10.x + m10.y) + (m11.x + m11.y))
                      + ((m12.x + m12.y) + (m13.x + m13.y));

        float act0, act1;
        if (is_tanh_gate) { act0 = tanhf_fast(g0); act1 = tanhf_fast(g1); }
        else              { act0 = sigf(g0);       act1 = sigf(g1);       }
        sm[OFF_G + 0 * 512 + j] = act0;
        sm[OFF_G + 1 * 512 + j] = act1;
        __syncthreads();   // barrier 1: acts visible

        if (tid < 256) {
            float ai = sm[OFF_G + r2 * 512 + k];
            float af = sm[OFF_G + r2 * 512 + 128 + k];
            float ag = sm[OFF_G + r2 * 512 + 256 + k];
            float ao = sm[OFF_G + r2 * 512 + 384 + k];
            cst = af * cst + ai * ag;
            float hval = ao * tanhf_fast(cst);
            h16[r2 * 128 + k] = __float2half(hval);
        }
        __syncthreads();   // barrier 2: h16 ready

        if (wrp == 8 || wrp == 9) {
            int row = wrp - 8;
            float2 ha = __half22float2(*(const __half2*)(h16 + row * 128 + lane * 4));
            float2 hb = __half22float2(*(const __half2*)(h16 + row * 128 + lane * 4 + 2));
            float v = ha.x * wo4.x + ha.y * wo4.y + hb.x * wo4.z + hb.y * wo4.w;
            v += __shfl_down_sync(0xffffffffu, v, 16);
            v += __shfl_down_sync(0xffffffffu, v, 8);
            v += __shfl_down_sync(0xffffffffu, v, 4);
            v += __shfl_down_sync(0xffffffffu, v, 2);
            v += __shfl_down_sync(0xffffffffu, v, 1);
            if (lane == 0) out[(size_t)(b0 + row) * Tt + t] = v + bo;
        }
    }
}

// ============================================================================
// launch — single fused kernel
// ============================================================================
extern "C" void kernel_launch(void* const* d_in, const int* in_sizes, int n_in,
                              void* d_out, int out_size)
{
    const float* x_dyn = (const float*)d_in[0];
    const float* x_sta = (const float*)d_in[1];
    const float* W_ih  = (const float*)d_in[2];
    const float* W_hh  = (const float*)d_in[3];
    const float* W_zh  = (const float*)d_in[4];
    const float* bvec  = (const float*)d_in[5];
    const float* W_out = (const float*)d_in[6];
    const float* b_out = (const float*)d_in[7];
    float* out = (float*)d_out;

    (void)in_sizes; (void)n_in; (void)out_size;

    cudaFuncSetAttribute(fused_kernel,
                         cudaFuncAttributeMaxDynamicSharedMemorySize, FUSED_SMEM);

    fused_kernel<<<128, 512, FUSED_SMEM>>>(
        x_dyn, W_ih, x_sta, W_zh, bvec, W_hh, W_out, b_out, out);
}